// round 8
// baseline (speedup 1.0000x reference)
#include <cuda_runtime.h>

// PS-ROI-Align, fixed dims:
//   input: (N=4, C=490, H=100, W=100) f32
//   rois:  (K=2048, 5) f32  [batch, x1, y1, x2, y2]
//   out:   (K, 10, 7, 7) f32,  POOL=7, SCALE=1/16, GRID=2
//
// 2 elements per thread, ALL loads for both elements front-batched and
// flat-predicated (rows 0,1 always; rows 2,3 act-predicated; 2nd float4
// need-predicated; rare 9th tap via predicated scalar load -> no fallback
// branch at all). 128-thread blocks, 2 blocks per roi.

#define C_TOT   490
#define HH      100
#define WW      100
#define POOL    7
#define SSCALE  0.0625f
#define PLANE   (HH * WW)

struct ElemState {
    const float4* p0;
    const float4* p1;
    const float4* p2;
    const float4* p3;
    bool act2, act3, needB, needC;
    float wr0, wr1, wr2, wr3;
    float fx0, fx1;
    int o_l0, o_h0, o_l1, o_h1;
};

__device__ __forceinline__ ElemState prep_elem(
    const float* __restrict__ baseimg, int r,
    float x1, float y1, float bsw, float bsh)
{
    ElemState s;
    int pw = r % POOL;
    int ph = (r / POOL) % POOL;

    const float* base = baseimg + r * PLANE;

    // x taps (samples at +0.25, +0.75 of bin)
    float tx0 = fmaxf(x1 + ((float)pw + 0.25f) * bsw, 0.0f);
    float tx1 = fmaxf(x1 + ((float)pw + 0.75f) * bsw, 0.0f);
    int xl0 = min((int)tx0, WW - 1);
    int xl1 = min((int)tx1, WW - 1);
    int xh0 = min(xl0 + 1, WW - 1);
    int xh1 = min(xl1 + 1, WW - 1);
    s.fx0 = (xl0 >= WW - 1) ? 0.0f : tx0 - (float)xl0;
    s.fx1 = (xl1 >= WW - 1) ? 0.0f : tx1 - (float)xl1;

    // y taps
    float ty0 = fmaxf(y1 + ((float)ph + 0.25f) * bsh, 0.0f);
    float ty1 = fmaxf(y1 + ((float)ph + 0.75f) * bsh, 0.0f);
    int yl0 = min((int)ty0, HH - 1);
    int yl1 = min((int)ty1, HH - 1);
    int yh0 = min(yl0 + 1, HH - 1);
    int yh1 = min(yl1 + 1, HH - 1);
    float fy0 = (yl0 >= HH - 1) ? 0.0f : ty0 - (float)yl0;
    float fy1 = (yl1 >= HH - 1) ? 0.0f : ty1 - (float)yl1;

    float a0 = 1.0f - fy0, a1 = fy0;
    float a2 = 1.0f - fy1, a3 = fy1;

    // branch-free row dedup
    bool same_pair = (yl1 == yl0);
    bool shift_one = (yl1 == yh0);
    s.act2 = !same_pair;
    s.act3 = !same_pair && !shift_one;
    int row2 = shift_one ? yh1 : yl1;
    s.wr0 = a0 + (same_pair ? a2 : 0.0f);
    s.wr1 = a1 + (same_pair ? a3 : (shift_one ? a2 : 0.0f));
    s.wr2 = shift_one ? a3 : a2;   // A2/B2/C2 zeroed when !act2
    s.wr3 = a3;                    // A3/B3/C3 zeroed when !act3

    // aligned x window: [wbase, wbase+11] always covers all taps
    // (o_h1 <= 8 provably; needC => xh1 = wbase+8 <= 99 => in-bounds)
    int wbase = xl0 & ~3;
    s.o_l0 = xl0 - wbase; s.o_h0 = xh0 - wbase;
    s.o_l1 = xl1 - wbase; s.o_h1 = xh1 - wbase;
    s.needB = (s.o_h1 > 3);
    s.needC = (s.o_h1 > 7);        // == 8

    const float* rowbase = base + wbase;
    s.p0 = (const float4*)(rowbase + yl0 * WW);
    s.p1 = (const float4*)(rowbase + yh0 * WW);
    s.p2 = (const float4*)(rowbase + row2 * WW);
    s.p3 = (const float4*)(rowbase + yh1 * WW);
    return s;
}

__device__ __forceinline__ float reduce_elem(
    const ElemState& s,
    float4 A0, float4 A1, float4 A2, float4 A3,
    float4 B0, float4 B1, float4 B2, float4 B3,
    float c0, float c1, float c2, float c3)
{
    // x-weight vector over window floats 0..7 (tap at 8 handled via C)
    float w[8];
    #pragma unroll
    for (int j = 0; j < 8; ++j) {
        float v = (j == s.o_l0) ? (1.0f - s.fx0) : 0.0f;
        v += (j == s.o_h0) ? s.fx0 : 0.0f;
        v += (j == s.o_l1) ? (1.0f - s.fx1) : 0.0f;
        v += (j == s.o_h1) ? s.fx1 : 0.0f;
        w[j] = v;
    }

    float ax = s.wr0 * A0.x + s.wr1 * A1.x + s.wr2 * A2.x + s.wr3 * A3.x;
    float ay = s.wr0 * A0.y + s.wr1 * A1.y + s.wr2 * A2.y + s.wr3 * A3.y;
    float az = s.wr0 * A0.z + s.wr1 * A1.z + s.wr2 * A2.z + s.wr3 * A3.z;
    float aw = s.wr0 * A0.w + s.wr1 * A1.w + s.wr2 * A2.w + s.wr3 * A3.w;
    float bx = s.wr0 * B0.x + s.wr1 * B1.x + s.wr2 * B2.x + s.wr3 * B3.x;
    float by = s.wr0 * B0.y + s.wr1 * B1.y + s.wr2 * B2.y + s.wr3 * B3.y;
    float bz = s.wr0 * B0.z + s.wr1 * B1.z + s.wr2 * B2.z + s.wr3 * B3.z;
    float bw = s.wr0 * B0.w + s.wr1 * B1.w + s.wr2 * B2.w + s.wr3 * B3.w;
    float cc = s.wr0 * c0   + s.wr1 * c1   + s.wr2 * c2   + s.wr3 * c3;

    float acc = ax * w[0] + ay * w[1] + az * w[2] + aw * w[3]
              + bx * w[4] + by * w[5] + bz * w[6] + bw * w[7]
              + (s.needC ? cc * s.fx1 : 0.0f);
    return acc * 0.25f;
}

__global__ __launch_bounds__(128, 4) void psroi_align_kernel(
    const float* __restrict__ input,
    const float* __restrict__ rois,
    float* __restrict__ out)
{
    int k = blockIdx.x >> 1;
    int j = blockIdx.x & 1;
    int t = threadIdx.x;

    const float* roi = rois + k * 5;
    int   b  = (int)__ldg(roi + 0);
    float x1 = __ldg(roi + 1) * SSCALE - 0.5f;
    float y1 = __ldg(roi + 2) * SSCALE - 0.5f;
    float x2 = __ldg(roi + 3) * SSCALE - 0.5f;
    float y2 = __ldg(roi + 4) * SSCALE - 0.5f;

    float bsh = (y2 - y1) * (1.0f / POOL);
    float bsw = (x2 - x1) * (1.0f / POOL);

    const float* baseimg = input + (long)b * C_TOT * PLANE;

    int r0 = (j << 7) + t;                 // [0, 255] always valid
    int r1full = 256 + (j << 7) + t;       // [256, 511]
    int r1 = min(r1full, C_TOT - 1);

    ElemState s0 = prep_elem(baseimg, r0, x1, y1, bsw, bsh);
    ElemState s1 = prep_elem(baseimg, r1, x1, y1, bsw, bsh);

    // ================= front-batched predicated loads ====================
    float4 Z = make_float4(0.f, 0.f, 0.f, 0.f);

    float4 eA0_0 = __ldg(s0.p0);
    float4 eA0_1 = __ldg(s0.p1);
    float4 eA1_0 = __ldg(s1.p0);
    float4 eA1_1 = __ldg(s1.p1);
    float4 eA0_2 = s0.act2 ? __ldg(s0.p2) : Z;
    float4 eA0_3 = s0.act3 ? __ldg(s0.p3) : Z;
    float4 eA1_2 = s1.act2 ? __ldg(s1.p2) : Z;
    float4 eA1_3 = s1.act3 ? __ldg(s1.p3) : Z;

    float4 eB0_0 = s0.needB ? __ldg(s0.p0 + 1) : Z;
    float4 eB0_1 = s0.needB ? __ldg(s0.p1 + 1) : Z;
    float4 eB0_2 = (s0.needB && s0.act2) ? __ldg(s0.p2 + 1) : Z;
    float4 eB0_3 = (s0.needB && s0.act3) ? __ldg(s0.p3 + 1) : Z;
    float4 eB1_0 = s1.needB ? __ldg(s1.p0 + 1) : Z;
    float4 eB1_1 = s1.needB ? __ldg(s1.p1 + 1) : Z;
    float4 eB1_2 = (s1.needB && s1.act2) ? __ldg(s1.p2 + 1) : Z;
    float4 eB1_3 = (s1.needB && s1.act3) ? __ldg(s1.p3 + 1) : Z;

    float eC0_0 = s0.needC ? __ldg((const float*)s0.p0 + 8) : 0.f;
    float eC0_1 = s0.needC ? __ldg((const float*)s0.p1 + 8) : 0.f;
    float eC0_2 = (s0.needC && s0.act2) ? __ldg((const float*)s0.p2 + 8) : 0.f;
    float eC0_3 = (s0.needC && s0.act3) ? __ldg((const float*)s0.p3 + 8) : 0.f;
    float eC1_0 = s1.needC ? __ldg((const float*)s1.p0 + 8) : 0.f;
    float eC1_1 = s1.needC ? __ldg((const float*)s1.p1 + 8) : 0.f;
    float eC1_2 = (s1.needC && s1.act2) ? __ldg((const float*)s1.p2 + 8) : 0.f;
    float eC1_3 = (s1.needC && s1.act3) ? __ldg((const float*)s1.p3 + 8) : 0.f;
    // =====================================================================

    float v0 = reduce_elem(s0, eA0_0, eA0_1, eA0_2, eA0_3,
                               eB0_0, eB0_1, eB0_2, eB0_3,
                               eC0_0, eC0_1, eC0_2, eC0_3);
    float v1 = reduce_elem(s1, eA1_0, eA1_1, eA1_2, eA1_3,
                               eB1_0, eB1_1, eB1_2, eB1_3,
                               eC1_0, eC1_1, eC1_2, eC1_3);

    out[k * C_TOT + r0] = v0;
    if (r1full < C_TOT)
        out[k * C_TOT + r1full] = v1;
}

extern "C" void kernel_launch(void* const* d_in, const int* in_sizes, int n_in,
                              void* d_out, int out_size)
{
    const float* input = (const float*)d_in[0];
    const float* rois  = (const float*)d_in[1];
    float* out = (float*)d_out;

    psroi_align_kernel<<<2048 * 2, 128>>>(input, rois, out);
}

// round 9
// speedup vs baseline: 1.0094x; 1.0094x over previous
#include <cuda_runtime.h>

// PS-ROI-Align, fixed dims:
//   input: (N=4, C=490, H=100, W=100) f32
//   rois:  (K=2048, 5) f32  [batch, x1, y1, x2, y2]
//   out:   (K, 10, 7, 7) f32,  POOL=7, SCALE=1/16, GRID=2
//
// Persistent kernel: 592 CTAs (4 per SM) x 256 threads, grid-stride loop.
// Per element: minimal predicated load set (rows 0,1 always; rows 2,3
// act-predicated; 2nd float4 per row need-predicated; 9th-float tap via
// predicated scalar load -> fully branch-free), all loads front-batched.

#define C_TOT   490
#define HH      100
#define WW      100
#define POOL    7
#define SSCALE  0.0625f
#define PLANE   (HH * WW)
#define TOTAL   (2048 * C_TOT)

__global__ __launch_bounds__(256, 4) void psroi_align_kernel(
    const float* __restrict__ input,
    const float* __restrict__ rois,
    float* __restrict__ out)
{
    int stride = gridDim.x * blockDim.x;

    for (int idx = blockIdx.x * blockDim.x + threadIdx.x; idx < TOTAL; idx += stride) {
        int k = idx / C_TOT;
        int r = idx - k * C_TOT;          // channel index c
        int pw = r % POOL;
        int ph = (r / POOL) % POOL;

        const float* roi = rois + k * 5;
        int   b  = (int)__ldg(roi + 0);
        float x1 = __ldg(roi + 1) * SSCALE - 0.5f;
        float y1 = __ldg(roi + 2) * SSCALE - 0.5f;
        float x2 = __ldg(roi + 3) * SSCALE - 0.5f;
        float y2 = __ldg(roi + 4) * SSCALE - 0.5f;

        float bsh = (y2 - y1) * (1.0f / POOL);
        float bsw = (x2 - x1) * (1.0f / POOL);

        const float* base = input + ((long)b * C_TOT + r) * PLANE;

        // ---- x taps (samples at +0.25, +0.75 of bin) ----
        float tx0 = fmaxf(x1 + ((float)pw + 0.25f) * bsw, 0.0f);
        float tx1 = fmaxf(x1 + ((float)pw + 0.75f) * bsw, 0.0f);
        int xl0 = min((int)tx0, WW - 1);
        int xl1 = min((int)tx1, WW - 1);
        int xh0 = min(xl0 + 1, WW - 1);
        int xh1 = min(xl1 + 1, WW - 1);
        float fx0 = (xl0 >= WW - 1) ? 0.0f : tx0 - (float)xl0;
        float fx1 = (xl1 >= WW - 1) ? 0.0f : tx1 - (float)xl1;

        // ---- y taps ----
        float ty0 = fmaxf(y1 + ((float)ph + 0.25f) * bsh, 0.0f);
        float ty1 = fmaxf(y1 + ((float)ph + 0.75f) * bsh, 0.0f);
        int yl0 = min((int)ty0, HH - 1);
        int yl1 = min((int)ty1, HH - 1);
        int yh0 = min(yl0 + 1, HH - 1);
        int yh1 = min(yl1 + 1, HH - 1);
        float fy0 = (yl0 >= HH - 1) ? 0.0f : ty0 - (float)yl0;
        float fy1 = (yl1 >= HH - 1) ? 0.0f : ty1 - (float)yl1;

        float a0 = 1.0f - fy0, a1 = fy0;
        float a2 = 1.0f - fy1, a3 = fy1;

        // ---- branch-free row dedup ----
        bool same_pair = (yl1 == yl0);
        bool shift_one = (yl1 == yh0);
        bool act2 = !same_pair;
        bool act3 = !same_pair && !shift_one;
        int  row2 = shift_one ? yh1 : yl1;
        float wr0 = a0 + (same_pair ? a2 : 0.0f);
        float wr1 = a1 + (same_pair ? a3 : (shift_one ? a2 : 0.0f));
        float wr2 = shift_one ? a3 : a2;   // zeroed operands when !act2
        float wr3 = a3;                    // zeroed operands when !act3

        // ---- aligned x window (taps span <= 9 floats from wbase) ----
        int wbase = xl0 & ~3;
        int o_l0 = xl0 - wbase, o_h0 = xh0 - wbase;
        int o_l1 = xl1 - wbase, o_h1 = xh1 - wbase;
        bool needB = (o_h1 > 3);
        bool needC = (o_h1 > 7);           // == 8; xh1 in-bounds by construction

        const float* rowbase = base + wbase;
        const float4* p0 = (const float4*)(rowbase + yl0 * WW);
        const float4* p1 = (const float4*)(rowbase + yh0 * WW);
        const float4* p2 = (const float4*)(rowbase + row2 * WW);
        const float4* p3 = (const float4*)(rowbase + yh1 * WW);

        // ======== front-batched predicated loads, no math in between ========
        float4 Z  = make_float4(0.f, 0.f, 0.f, 0.f);
        float4 A0, A1, A2 = Z, A3 = Z, B0 = Z, B1 = Z, B2 = Z, B3 = Z;
        float  c0 = 0.f, c1 = 0.f, c2 = 0.f, c3 = 0.f;
        A0 = __ldg(p0);
        A1 = __ldg(p1);
        if (act2)          A2 = __ldg(p2);
        if (act3)          A3 = __ldg(p3);
        if (needB)         B0 = __ldg(p0 + 1);
        if (needB)         B1 = __ldg(p1 + 1);
        if (needB && act2) B2 = __ldg(p2 + 1);
        if (needB && act3) B3 = __ldg(p3 + 1);
        if (needC)         c0 = __ldg((const float*)p0 + 8);
        if (needC)         c1 = __ldg((const float*)p1 + 8);
        if (needC && act2) c2 = __ldg((const float*)p2 + 8);
        if (needC && act3) c3 = __ldg((const float*)p3 + 8);
        // ====================================================================

        // x-weight vector over window floats 0..7 (tap 8 via C scalars)
        float w[8];
        #pragma unroll
        for (int j = 0; j < 8; ++j) {
            float v = (j == o_l0) ? (1.0f - fx0) : 0.0f;
            v += (j == o_h0) ? fx0 : 0.0f;
            v += (j == o_l1) ? (1.0f - fx1) : 0.0f;
            v += (j == o_h1) ? fx1 : 0.0f;
            w[j] = v;
        }

        float ax = wr0 * A0.x + wr1 * A1.x + wr2 * A2.x + wr3 * A3.x;
        float ay = wr0 * A0.y + wr1 * A1.y + wr2 * A2.y + wr3 * A3.y;
        float az = wr0 * A0.z + wr1 * A1.z + wr2 * A2.z + wr3 * A3.z;
        float aw = wr0 * A0.w + wr1 * A1.w + wr2 * A2.w + wr3 * A3.w;
        float bx = wr0 * B0.x + wr1 * B1.x + wr2 * B2.x + wr3 * B3.x;
        float by = wr0 * B0.y + wr1 * B1.y + wr2 * B2.y + wr3 * B3.y;
        float bz = wr0 * B0.z + wr1 * B1.z + wr2 * B2.z + wr3 * B3.z;
        float bw = wr0 * B0.w + wr1 * B1.w + wr2 * B2.w + wr3 * B3.w;
        float cc = wr0 * c0   + wr1 * c1   + wr2 * c2   + wr3 * c3;

        float acc = ax * w[0] + ay * w[1] + az * w[2] + aw * w[3]
                  + bx * w[4] + by * w[5] + bz * w[6] + bw * w[7]
                  + (needC ? cc * fx1 : 0.0f);

        out[idx] = acc * 0.25f;
    }
}

extern "C" void kernel_launch(void* const* d_in, const int* in_sizes, int n_in,
                              void* d_out, int out_size)
{
    const float* input = (const float*)d_in[0];
    const float* rois  = (const float*)d_in[1];
    float* out = (float*)d_out;

    psroi_align_kernel<<<148 * 4, 256>>>(input, rois, out);
}

// round 10
// speedup vs baseline: 1.0106x; 1.0012x over previous
#include <cuda_runtime.h>

// PS-ROI-Align, fixed dims:
//   input: (N=4, C=490, H=100, W=100) f32
//   rois:  (K=2048, 5) f32  [batch, x1, y1, x2, y2]
//   out:   (K, 10, 7, 7) f32,  POOL=7, SCALE=1/16, GRID=2
//
// Two-kernel smem-staged design:
//   prep: bucket rois by batch (atomic slots; output-invariant order),
//         precompute per-roi (x1, y1, bsw, bsh).
//   main: block (r, b) loads plane (b, r) into 40KB smem with fully
//         coalesced float4 loads, then computes that channel's output for
//         every roi of batch b, sampling from smem (R9 predicated
//         aligned-window math). This collapses the per-element L1
//         gather-wavefront floor (~5.5/elem -> ~0.6/elem).

#define C_TOT   490
#define HH      100
#define WW      100
#define POOL    7
#define SSCALE  0.0625f
#define PLANE   (HH * WW)
#define K_ROIS  2048
#define NBATCH  4

__device__ int    g_count[NBATCH];
__device__ int    g_list[NBATCH][K_ROIS];
__device__ float4 g_par [NBATCH][K_ROIS];   // x1, y1, bsw, bsh

__global__ void prep_kernel(const float* __restrict__ rois)
{
    int t = threadIdx.x;
    if (t < NBATCH) g_count[t] = 0;
    __syncthreads();
    for (int k = t; k < K_ROIS; k += blockDim.x) {
        const float* roi = rois + k * 5;
        int   b  = (int)roi[0];
        float x1 = roi[1] * SSCALE - 0.5f;
        float y1 = roi[2] * SSCALE - 0.5f;
        float x2 = roi[3] * SSCALE - 0.5f;
        float y2 = roi[4] * SSCALE - 0.5f;
        int i = atomicAdd(&g_count[b], 1);
        g_list[b][i] = k;
        g_par[b][i]  = make_float4(x1, y1,
                                   (x2 - x1) * (1.0f / POOL),
                                   (y2 - y1) * (1.0f / POOL));
    }
}

__global__ __launch_bounds__(256) void psroi_main(
    const float* __restrict__ input,
    float* __restrict__ out)
{
    __shared__ float s_plane[PLANE + 16];   // +16 pad: B-loads may run 3 floats past row 99

    int r = blockIdx.x;          // channel / output slice index, 0..489
    int b = blockIdx.y;          // batch, 0..3
    int t = threadIdx.x;

    // ---- coalesced plane load: gmem -> smem ----
    const float4* src = (const float4*)(input + ((long)b * C_TOT + r) * PLANE);
    float4* dst = (float4*)s_plane;
    #pragma unroll
    for (int i = 0; i < PLANE / 4 / 256 + 1; ++i) {
        int j = t + i * 256;
        if (j < PLANE / 4) dst[j] = __ldg(src + j);
    }
    if (t < 16) s_plane[PLANE + t] = 0.0f;
    __syncthreads();

    // block-uniform bin coordinates
    int pw = r % POOL;
    int ph = (r / POOL) % POOL;
    float cpw0 = (float)pw + 0.25f, cpw1 = (float)pw + 0.75f;
    float cph0 = (float)ph + 0.25f, cph1 = (float)ph + 0.75f;

    int n = g_count[b];
    for (int i = t; i < n; i += 256) {
        int    k = g_list[b][i];
        float4 P = g_par[b][i];
        float x1 = P.x, y1 = P.y, bsw = P.z, bsh = P.w;

        // ---- x taps ----
        float tx0 = fmaxf(x1 + cpw0 * bsw, 0.0f);
        float tx1 = fmaxf(x1 + cpw1 * bsw, 0.0f);
        int xl0 = min((int)tx0, WW - 1);
        int xl1 = min((int)tx1, WW - 1);
        int xh0 = min(xl0 + 1, WW - 1);
        int xh1 = min(xl1 + 1, WW - 1);
        float fx0 = (xl0 >= WW - 1) ? 0.0f : tx0 - (float)xl0;
        float fx1 = (xl1 >= WW - 1) ? 0.0f : tx1 - (float)xl1;

        // ---- y taps ----
        float ty0 = fmaxf(y1 + cph0 * bsh, 0.0f);
        float ty1 = fmaxf(y1 + cph1 * bsh, 0.0f);
        int yl0 = min((int)ty0, HH - 1);
        int yl1 = min((int)ty1, HH - 1);
        int yh0 = min(yl0 + 1, HH - 1);
        int yh1 = min(yl1 + 1, HH - 1);
        float fy0 = (yl0 >= HH - 1) ? 0.0f : ty0 - (float)yl0;
        float fy1 = (yl1 >= HH - 1) ? 0.0f : ty1 - (float)yl1;

        float a0 = 1.0f - fy0, a1 = fy0;
        float a2 = 1.0f - fy1, a3 = fy1;

        // ---- branch-free row dedup ----
        bool same_pair = (yl1 == yl0);
        bool shift_one = (yl1 == yh0);
        bool act2 = !same_pair;
        bool act3 = !same_pair && !shift_one;
        int  row2 = shift_one ? yh1 : yl1;
        float wr0 = a0 + (same_pair ? a2 : 0.0f);
        float wr1 = a1 + (same_pair ? a3 : (shift_one ? a2 : 0.0f));
        float wr2 = shift_one ? a3 : a2;
        float wr3 = a3;

        // ---- aligned x window (row offsets are 16B aligned: 400B rows) ----
        int wbase = xl0 & ~3;
        int o_l0 = xl0 - wbase, o_h0 = xh0 - wbase;
        int o_l1 = xl1 - wbase, o_h1 = xh1 - wbase;
        bool needB = (o_h1 > 3);
        bool needC = (o_h1 > 7);        // == 8; xh1 = wbase+8 <= 99 in-row

        const float* rowbase = s_plane + wbase;
        const float4* p0 = (const float4*)(rowbase + yl0 * WW);
        const float4* p1 = (const float4*)(rowbase + yh0 * WW);
        const float4* p2 = (const float4*)(rowbase + row2 * WW);
        const float4* p3 = (const float4*)(rowbase + yh1 * WW);

        // ---- predicated smem loads ----
        float4 Z  = make_float4(0.f, 0.f, 0.f, 0.f);
        float4 A0, A1, A2 = Z, A3 = Z, B0 = Z, B1 = Z, B2 = Z, B3 = Z;
        float  c0 = 0.f, c1 = 0.f, c2 = 0.f, c3 = 0.f;
        A0 = *p0;
        A1 = *p1;
        if (act2)          A2 = *p2;
        if (act3)          A3 = *p3;
        if (needB)         B0 = p0[1];
        if (needB)         B1 = p1[1];
        if (needB && act2) B2 = p2[1];
        if (needB && act3) B3 = p3[1];
        if (needC)         c0 = ((const float*)p0)[8];
        if (needC)         c1 = ((const float*)p1)[8];
        if (needC && act2) c2 = ((const float*)p2)[8];
        if (needC && act3) c3 = ((const float*)p3)[8];

        // x-weight vector over window floats 0..7 (tap 8 via C scalars)
        float w[8];
        #pragma unroll
        for (int j = 0; j < 8; ++j) {
            float v = (j == o_l0) ? (1.0f - fx0) : 0.0f;
            v += (j == o_h0) ? fx0 : 0.0f;
            v += (j == o_l1) ? (1.0f - fx1) : 0.0f;
            v += (j == o_h1) ? fx1 : 0.0f;
            w[j] = v;
        }

        float ax = wr0 * A0.x + wr1 * A1.x + wr2 * A2.x + wr3 * A3.x;
        float ay = wr0 * A0.y + wr1 * A1.y + wr2 * A2.y + wr3 * A3.y;
        float az = wr0 * A0.z + wr1 * A1.z + wr2 * A2.z + wr3 * A3.z;
        float aw = wr0 * A0.w + wr1 * A1.w + wr2 * A2.w + wr3 * A3.w;
        float bx = wr0 * B0.x + wr1 * B1.x + wr2 * B2.x + wr3 * B3.x;
        float by = wr0 * B0.y + wr1 * B1.y + wr2 * B2.y + wr3 * B3.y;
        float bz = wr0 * B0.z + wr1 * B1.z + wr2 * B2.z + wr3 * B3.z;
        float bw = wr0 * B0.w + wr1 * B1.w + wr2 * B2.w + wr3 * B3.w;
        float cc = wr0 * c0   + wr1 * c1   + wr2 * c2   + wr3 * c3;

        float acc = ax * w[0] + ay * w[1] + az * w[2] + aw * w[3]
                  + bx * w[4] + by * w[5] + bz * w[6] + bw * w[7]
                  + (needC ? cc * fx1 : 0.0f);

        out[k * C_TOT + r] = acc * 0.25f;
    }
}

extern "C" void kernel_launch(void* const* d_in, const int* in_sizes, int n_in,
                              void* d_out, int out_size)
{
    const float* input = (const float*)d_in[0];
    const float* rois  = (const float*)d_in[1];
    float* out = (float*)d_out;

    prep_kernel<<<1, 512>>>(rois);
    dim3 grid(C_TOT, NBATCH);
    psroi_main<<<grid, 256>>>(input, out);
}

// round 11
// speedup vs baseline: 1.1774x; 1.1651x over previous
#include <cuda_runtime.h>

// PS-ROI-Align, fixed dims:
//   input: (N=4, C=490, H=100, W=100) f32
//   rois:  (K=2048, 5) f32  [batch, x1, y1, x2, y2]
//   out:   (K, 10, 7, 7) f32,  POOL=7, SCALE=1/16, GRID=2
//
// Two-kernel smem-staged design (R10) + cp.async plane loads + occupancy fix:
//   prep: bucket rois by batch, precompute per-roi (x1, y1, bsw, bsh).
//   main: block (r, b) stages plane (b, r) into 40KB smem via cp.async
//         (no register staging), computes channel r's output for every roi
//         of batch b from smem. __launch_bounds__(256,4) -> 4 CTAs/SM.

#define C_TOT   490
#define HH      100
#define WW      100
#define POOL    7
#define SSCALE  0.0625f
#define PLANE   (HH * WW)
#define K_ROIS  2048
#define NBATCH  4

__device__ int    g_count[NBATCH];
__device__ int    g_list[NBATCH][K_ROIS];
__device__ float4 g_par [NBATCH][K_ROIS];   // x1, y1, bsw, bsh

__global__ void prep_kernel(const float* __restrict__ rois)
{
    int t = threadIdx.x;
    if (t < NBATCH) g_count[t] = 0;
    __syncthreads();
    for (int k = t; k < K_ROIS; k += blockDim.x) {
        const float* roi = rois + k * 5;
        int   b  = (int)roi[0];
        float x1 = roi[1] * SSCALE - 0.5f;
        float y1 = roi[2] * SSCALE - 0.5f;
        float x2 = roi[3] * SSCALE - 0.5f;
        float y2 = roi[4] * SSCALE - 0.5f;
        int i = atomicAdd(&g_count[b], 1);
        g_list[b][i] = k;
        g_par[b][i]  = make_float4(x1, y1,
                                   (x2 - x1) * (1.0f / POOL),
                                   (y2 - y1) * (1.0f / POOL));
    }
}

__global__ __launch_bounds__(256, 4) void psroi_main(
    const float* __restrict__ input,
    float* __restrict__ out)
{
    __shared__ float s_plane[PLANE + 16];   // +16 pad: B/C taps may run past row 99

    int r = blockIdx.x;          // channel / output slice index, 0..489
    int b = blockIdx.y;          // batch, 0..3
    int t = threadIdx.x;

    // ---- async coalesced plane load: gmem -> smem, no register staging ----
    {
        const float4* src = (const float4*)(input + ((long)b * C_TOT + r) * PLANE);
        float4* dst = (float4*)s_plane;
        #pragma unroll
        for (int i = 0; i < 10; ++i) {               // 2500 float4 / 256 thr
            int j = t + i * 256;
            if (j < PLANE / 4) {
                unsigned saddr = (unsigned)__cvta_generic_to_shared(dst + j);
                asm volatile("cp.async.cg.shared.global [%0], [%1], 16;\n"
                             :: "r"(saddr), "l"(src + j) : "memory");
            }
        }
        asm volatile("cp.async.commit_group;\n" ::: "memory");
    }
    if (t < 16) s_plane[PLANE + t] = 0.0f;

    // block-uniform bin coordinates (computed while loads are in flight)
    int pw = r % POOL;
    int ph = (r / POOL) % POOL;
    float cpw0 = (float)pw + 0.25f, cpw1 = (float)pw + 0.75f;
    float cph0 = (float)ph + 0.25f, cph1 = (float)ph + 0.75f;
    int n = g_count[b];

    asm volatile("cp.async.wait_group 0;\n" ::: "memory");
    __syncthreads();

    for (int i = t; i < n; i += 256) {
        int    k = g_list[b][i];
        float4 P = g_par[b][i];
        float x1 = P.x, y1 = P.y, bsw = P.z, bsh = P.w;

        // ---- x taps ----
        float tx0 = fmaxf(x1 + cpw0 * bsw, 0.0f);
        float tx1 = fmaxf(x1 + cpw1 * bsw, 0.0f);
        int xl0 = min((int)tx0, WW - 1);
        int xl1 = min((int)tx1, WW - 1);
        int xh0 = min(xl0 + 1, WW - 1);
        int xh1 = min(xl1 + 1, WW - 1);
        float fx0 = (xl0 >= WW - 1) ? 0.0f : tx0 - (float)xl0;
        float fx1 = (xl1 >= WW - 1) ? 0.0f : tx1 - (float)xl1;

        // ---- y taps ----
        float ty0 = fmaxf(y1 + cph0 * bsh, 0.0f);
        float ty1 = fmaxf(y1 + cph1 * bsh, 0.0f);
        int yl0 = min((int)ty0, HH - 1);
        int yl1 = min((int)ty1, HH - 1);
        int yh0 = min(yl0 + 1, HH - 1);
        int yh1 = min(yl1 + 1, HH - 1);
        float fy0 = (yl0 >= HH - 1) ? 0.0f : ty0 - (float)yl0;
        float fy1 = (yl1 >= HH - 1) ? 0.0f : ty1 - (float)yl1;

        float a0 = 1.0f - fy0, a1 = fy0;
        float a2 = 1.0f - fy1, a3 = fy1;

        // ---- branch-free row dedup ----
        bool same_pair = (yl1 == yl0);
        bool shift_one = (yl1 == yh0);
        bool act2 = !same_pair;
        bool act3 = !same_pair && !shift_one;
        int  row2 = shift_one ? yh1 : yl1;
        float wr0 = a0 + (same_pair ? a2 : 0.0f);
        float wr1 = a1 + (same_pair ? a3 : (shift_one ? a2 : 0.0f));
        float wr2 = shift_one ? a3 : a2;
        float wr3 = a3;

        // ---- aligned x window (rows are 400B -> 16B aligned) ----
        int wbase = xl0 & ~3;
        int o_l0 = xl0 - wbase, o_h0 = xh0 - wbase;
        int o_l1 = xl1 - wbase, o_h1 = xh1 - wbase;
        bool needB = (o_h1 > 3);
        bool needC = (o_h1 > 7);        // == 8

        const float* rowbase = s_plane + wbase;
        const float4* p0 = (const float4*)(rowbase + yl0 * WW);
        const float4* p1 = (const float4*)(rowbase + yh0 * WW);
        const float4* p2 = (const float4*)(rowbase + row2 * WW);
        const float4* p3 = (const float4*)(rowbase + yh1 * WW);

        // ---- predicated smem loads ----
        float4 Z  = make_float4(0.f, 0.f, 0.f, 0.f);
        float4 A0, A1, A2 = Z, A3 = Z, B0 = Z, B1 = Z, B2 = Z, B3 = Z;
        float  c0 = 0.f, c1 = 0.f, c2 = 0.f, c3 = 0.f;
        A0 = *p0;
        A1 = *p1;
        if (act2)          A2 = *p2;
        if (act3)          A3 = *p3;
        if (needB)         B0 = p0[1];
        if (needB)         B1 = p1[1];
        if (needB && act2) B2 = p2[1];
        if (needB && act3) B3 = p3[1];
        if (needC)         c0 = ((const float*)p0)[8];
        if (needC)         c1 = ((const float*)p1)[8];
        if (needC && act2) c2 = ((const float*)p2)[8];
        if (needC && act3) c3 = ((const float*)p3)[8];

        // x-weight vector over window floats 0..7 (tap 8 via C scalars)
        float w[8];
        #pragma unroll
        for (int j = 0; j < 8; ++j) {
            float v = (j == o_l0) ? (1.0f - fx0) : 0.0f;
            v += (j == o_h0) ? fx0 : 0.0f;
            v += (j == o_l1) ? (1.0f - fx1) : 0.0f;
            v += (j == o_h1) ? fx1 : 0.0f;
            w[j] = v;
        }

        float ax = wr0 * A0.x + wr1 * A1.x + wr2 * A2.x + wr3 * A3.x;
        float ay = wr0 * A0.y + wr1 * A1.y + wr2 * A2.y + wr3 * A3.y;
        float az = wr0 * A0.z + wr1 * A1.z + wr2 * A2.z + wr3 * A3.z;
        float aw = wr0 * A0.w + wr1 * A1.w + wr2 * A2.w + wr3 * A3.w;
        float bx = wr0 * B0.x + wr1 * B1.x + wr2 * B2.x + wr3 * B3.x;
        float by = wr0 * B0.y + wr1 * B1.y + wr2 * B2.y + wr3 * B3.y;
        float bz = wr0 * B0.z + wr1 * B1.z + wr2 * B2.z + wr3 * B3.z;
        float bw = wr0 * B0.w + wr1 * B1.w + wr2 * B2.w + wr3 * B3.w;
        float cc = wr0 * c0   + wr1 * c1   + wr2 * c2   + wr3 * c3;

        float acc = ax * w[0] + ay * w[1] + az * w[2] + aw * w[3]
                  + bx * w[4] + by * w[5] + bz * w[6] + bw * w[7]
                  + (needC ? cc * fx1 : 0.0f);

        out[k * C_TOT + r] = acc * 0.25f;
    }
}

extern "C" void kernel_launch(void* const* d_in, const int* in_sizes, int n_in,
                              void* d_out, int out_size)
{
    const float* input = (const float*)d_in[0];
    const float* rois  = (const float*)d_in[1];
    float* out = (float*)d_out;

    prep_kernel<<<1, 512>>>(rois);
    dim3 grid(C_TOT, NBATCH);
    psroi_main<<<grid, 256>>>(input, out);
}